// round 1
// baseline (speedup 1.0000x reference)
#include <cuda_runtime.h>
#include <cuda_bf16.h>
#include <cstdint>

// ---------------------------------------------------------------------------
// MultimodalGCN forward on GB300.
//   Pipeline:
//     deg/dinv -> CSR build -> agg(x,128) -> GEMM1(+BN+ReLU) -> agg(h1,256)
//     -> GEMM2(+BN+ReLU+residual) -> per-graph mean pool -> MLP head
//   Output: d_out[0 : B*2]        = logits
//           d_out[B*2 : B*2+B*H]  = emb
// ---------------------------------------------------------------------------

#define MAXN 100000
#define MAXE 1600000
#define MAXB 256
#define HDIM 256
#define DIN  128
#define BN_EPS 1e-5f

// scratch (device globals: allocation-free contract)
__device__ __align__(16) float g_deg[MAXN];
__device__ __align__(16) float g_dinv[MAXN];
__device__ int   g_cnt[MAXN];
__device__ int   g_rowptr[MAXN + 1];
__device__ int   g_fill[MAXN];
__device__ int   g_src[MAXE];
__device__ __align__(16) float g_w[MAXE];
__device__ __align__(16) float g_ax[(size_t)MAXN * DIN];
__device__ __align__(16) float g_h1[(size_t)MAXN * HDIM];
__device__ __align__(16) float g_ah[(size_t)MAXN * HDIM];
__device__ __align__(16) float g_h2[(size_t)MAXN * HDIM];
__device__ __align__(16) float g_emb[MAXB * HDIM];
__device__ __align__(16) float g_z1[MAXB * 256];
__device__ __align__(16) float g_z2[MAXB * 128];
__device__ int g_gcnt[MAXB];
__device__ int g_goff[MAXB];

// ---------------------------------------------------------------------------
__global__ void zero_kernel(int n, int b) {
    int i = blockIdx.x * blockDim.x + threadIdx.x;
    if (i < n) { g_deg[i] = 0.f; g_cnt[i] = 0; g_fill[i] = 0; }
    if (i < b) { g_gcnt[i] = 0; }
}

__global__ void deg_kernel(const int* __restrict__ ei, const float* __restrict__ ew, int E) {
    int e = blockIdx.x * blockDim.x + threadIdx.x;
    if (e >= E) return;
    int d = ei[E + e];
    atomicAdd(&g_deg[d], ew[e]);
    atomicAdd(&g_cnt[d], 1);
}

__global__ void dinv_kernel(int n) {
    int i = blockIdx.x * blockDim.x + threadIdx.x;
    if (i < n) g_dinv[i] = rsqrtf(g_deg[i] + 1.0f);
}

// single-block exclusive scan of g_cnt -> g_rowptr (warp-scan based)
__global__ void scan_rowptr_kernel(int n) {
    __shared__ int wsum[32];
    __shared__ int carry_s;
    int tid = threadIdx.x, lane = tid & 31, wid = tid >> 5;
    if (tid == 0) carry_s = 0;
    __syncthreads();
    for (int base = 0; base < n; base += 1024) {
        int i = base + tid;
        int v = (i < n) ? g_cnt[i] : 0;
        int x = v;
        #pragma unroll
        for (int off = 1; off < 32; off <<= 1) {
            int y = __shfl_up_sync(0xFFFFFFFFu, x, off);
            if (lane >= off) x += y;
        }
        if (lane == 31) wsum[wid] = x;
        __syncthreads();
        if (wid == 0) {
            int s = wsum[lane];
            int t = s;
            #pragma unroll
            for (int off = 1; off < 32; off <<= 1) {
                int y = __shfl_up_sync(0xFFFFFFFFu, t, off);
                if (lane >= off) t += y;
            }
            wsum[lane] = t - s;   // exclusive warp offsets
        }
        __syncthreads();
        int incl = x + wsum[wid];
        int carry = carry_s;
        if (i < n) g_rowptr[i] = carry + incl - v;
        __syncthreads();
        if (tid == 1023) carry_s = carry + incl;
        __syncthreads();
    }
    if (threadIdx.x == 0) g_rowptr[n] = carry_s;
}

__global__ void fill_kernel(const int* __restrict__ ei, const float* __restrict__ ew, int E) {
    int e = blockIdx.x * blockDim.x + threadIdx.x;
    if (e >= E) return;
    int s = ei[e];
    int d = ei[E + e];
    int pos = g_rowptr[d] + atomicAdd(&g_fill[d], 1);
    g_src[pos] = s;
    g_w[pos] = g_dinv[s] * ew[e];
}

// agg[d] = dinv[d]*sum_e w_e*feat[src_e] + dinv[d]^2*feat[d]; one warp per node
template<int D>
__global__ void agg_kernel(const float* __restrict__ feat, float* __restrict__ out, int n) {
    int warp = (blockIdx.x * blockDim.x + threadIdx.x) >> 5;
    int lane = threadIdx.x & 31;
    if (warp >= n) return;
    const int V = D / 128;  // float4 per lane
    float4 acc[V];
    #pragma unroll
    for (int v = 0; v < V; v++) acc[v] = make_float4(0.f, 0.f, 0.f, 0.f);
    int beg = g_rowptr[warp], end = g_rowptr[warp + 1];
    for (int e = beg; e < end; e++) {
        int s = g_src[e];
        float w = g_w[e];
        const float4* fp = (const float4*)(feat + (size_t)s * D);
        #pragma unroll
        for (int v = 0; v < V; v++) {
            float4 f = fp[lane + v * 32];
            acc[v].x += w * f.x; acc[v].y += w * f.y;
            acc[v].z += w * f.z; acc[v].w += w * f.w;
        }
    }
    float di = g_dinv[warp];
    float di2 = di * di;
    const float4* fs = (const float4*)(feat + (size_t)warp * D);
    float4* op = (float4*)(out + (size_t)warp * D);
    #pragma unroll
    for (int v = 0; v < V; v++) {
        float4 f = fs[lane + v * 32];
        float4 r;
        r.x = di * acc[v].x + di2 * f.x;
        r.y = di * acc[v].y + di2 * f.y;
        r.z = di * acc[v].z + di2 * f.z;
        r.w = di * acc[v].w + di2 * f.w;
        op[lane + v * 32] = r;
    }
}

// out = relu((A@W + bias - rm)*g*rsqrt(rv+eps) + be) [+ resid];  W is [K,256]
template<int K>
__global__ __launch_bounds__(256) void gemm_bn_relu(
    const float* __restrict__ A, const float* __restrict__ W,
    const float* __restrict__ bias, const float* __restrict__ gam,
    const float* __restrict__ bet, const float* __restrict__ rm,
    const float* __restrict__ rv, const float* __restrict__ resid,
    float* __restrict__ out, int M)
{
    const int BM = 128, BK = 16;
    __shared__ __align__(16) float As[BK][BM + 4];
    __shared__ __align__(16) float Bs[BK][128];
    int tid = threadIdx.x;
    int tx = tid & 15, ty = tid >> 4;
    int m0 = blockIdx.y * BM, n0 = blockIdx.x * 128;
    float c[8][8] = {};
    for (int k0 = 0; k0 < K; k0 += BK) {
        #pragma unroll
        for (int q = tid; q < 512; q += 256) {
            int row = q >> 2, cf = q & 3;
            int grow = m0 + row;
            float4 a = (grow < M) ? *(const float4*)(A + (size_t)grow * K + k0 + cf * 4)
                                  : make_float4(0.f, 0.f, 0.f, 0.f);
            As[cf * 4 + 0][row] = a.x; As[cf * 4 + 1][row] = a.y;
            As[cf * 4 + 2][row] = a.z; As[cf * 4 + 3][row] = a.w;
        }
        #pragma unroll
        for (int q = tid; q < 512; q += 256) {
            int row = q >> 5, cf = q & 31;
            *(float4*)&Bs[row][cf * 4] =
                *(const float4*)(W + (size_t)(k0 + row) * 256 + n0 + cf * 4);
        }
        __syncthreads();
        #pragma unroll
        for (int k = 0; k < BK; k++) {
            float a[8], b[8];
            *(float4*)&a[0] = *(const float4*)&As[k][ty * 8];
            *(float4*)&a[4] = *(const float4*)&As[k][ty * 8 + 4];
            *(float4*)&b[0] = *(const float4*)&Bs[k][tx * 8];
            *(float4*)&b[4] = *(const float4*)&Bs[k][tx * 8 + 4];
            #pragma unroll
            for (int i = 0; i < 8; i++)
                #pragma unroll
                for (int j = 0; j < 8; j++)
                    c[i][j] += a[i] * b[j];
        }
        __syncthreads();
    }
    float sc[8], sh[8];
    #pragma unroll
    for (int j = 0; j < 8; j++) {
        int n = n0 + tx * 8 + j;
        float s = gam[n] * rsqrtf(rv[n] + BN_EPS);
        sc[j] = s;
        sh[j] = (bias[n] - rm[n]) * s + bet[n];
    }
    #pragma unroll
    for (int i = 0; i < 8; i++) {
        int r = m0 + ty * 8 + i;
        if (r < M) {
            float v[8];
            #pragma unroll
            for (int j = 0; j < 8; j++) {
                float val = fmaxf(c[i][j] * sc[j] + sh[j], 0.f);
                if (resid) val += resid[(size_t)r * 256 + n0 + tx * 8 + j];
                v[j] = val;
            }
            *(float4*)(out + (size_t)r * 256 + n0 + tx * 8) = *(float4*)&v[0];
            *(float4*)(out + (size_t)r * 256 + n0 + tx * 8 + 4) = *(float4*)&v[4];
        }
    }
}

__global__ void gcount_kernel(const int* __restrict__ batch, int n) {
    int i = blockIdx.x * blockDim.x + threadIdx.x;
    if (i < n) atomicAdd(&g_gcnt[batch[i]], 1);
}

__global__ void scan_goff_kernel(int b) {   // single block, 256 threads
    __shared__ int wsum[8];
    int tid = threadIdx.x, lane = tid & 31, wid = tid >> 5;
    int v = (tid < b) ? g_gcnt[tid] : 0;
    int x = v;
    #pragma unroll
    for (int off = 1; off < 32; off <<= 1) {
        int y = __shfl_up_sync(0xFFFFFFFFu, x, off);
        if (lane >= off) x += y;
    }
    if (lane == 31) wsum[wid] = x;
    __syncthreads();
    if (tid == 0) {
        int s = 0;
        #pragma unroll
        for (int j = 0; j < 8; j++) { int t = wsum[j]; wsum[j] = s; s += t; }
    }
    __syncthreads();
    if (tid < b) g_goff[tid] = x - v + wsum[wid];
}

__global__ void pool_kernel(float* __restrict__ d_out, int B) {
    int g = blockIdx.x, c = threadIdx.x;
    int start = g_goff[g], cnt = g_gcnt[g];
    float s = 0.f;
    for (int n = 0; n < cnt; n++) s += g_h2[(size_t)(start + n) * HDIM + c];
    float e = s / fmaxf((float)cnt, 1.0f);
    g_emb[g * HDIM + c] = e;
    d_out[B * 2 + g * HDIM + c] = e;
}

__global__ void mlp_layer_kernel(const float* __restrict__ in, const float* __restrict__ W,
                                 const float* __restrict__ bias, const float* __restrict__ gam,
                                 const float* __restrict__ bet, const float* __restrict__ rm,
                                 const float* __restrict__ rv, float* __restrict__ out,
                                 int K, int Nout) {
    __shared__ float sh[256];
    int r = blockIdx.x, j = threadIdx.x;
    for (int k = j; k < K; k += blockDim.x) sh[k] = in[r * K + k];
    __syncthreads();
    float acc = 0.f;
    for (int k = 0; k < K; k++) acc += sh[k] * W[k * Nout + j];
    float s = gam[j] * rsqrtf(rv[j] + BN_EPS);
    float val = (acc + bias[j] - rm[j]) * s + bet[j];
    out[r * Nout + j] = fmaxf(val, 0.f);
}

__global__ void logits_kernel(const float* __restrict__ W3, const float* __restrict__ b3,
                              float* __restrict__ d_out, int B) {
    int t = blockIdx.x * blockDim.x + threadIdx.x;
    if (t >= B * 2) return;
    int r = t >> 1, o = t & 1;
    float acc = 0.f;
    #pragma unroll 4
    for (int k = 0; k < 128; k++) acc += g_z2[r * 128 + k] * W3[k * 2 + o];
    d_out[r * 2 + o] = acc + b3[o];
}

// ---------------------------------------------------------------------------
extern "C" void kernel_launch(void* const* d_in, const int* in_sizes, int n_in,
                              void* d_out, int out_size) {
    const float* x   = (const float*)d_in[0];
    const int*   ei  = (const int*)d_in[1];
    const float* ew  = (const float*)d_in[2];
    const int*   bat = (const int*)d_in[3];
    const float* W1  = (const float*)d_in[4];
    const float* b1  = (const float*)d_in[5];
    const float* g1  = (const float*)d_in[6];
    const float* be1 = (const float*)d_in[7];
    const float* rm1 = (const float*)d_in[8];
    const float* rv1 = (const float*)d_in[9];
    const float* W2  = (const float*)d_in[10];
    const float* b2  = (const float*)d_in[11];
    const float* g2  = (const float*)d_in[12];
    const float* be2 = (const float*)d_in[13];
    const float* rm2 = (const float*)d_in[14];
    const float* rv2 = (const float*)d_in[15];
    const float* cW1 = (const float*)d_in[16];
    const float* cb1 = (const float*)d_in[17];
    const float* cg1 = (const float*)d_in[18];
    const float* cbe1= (const float*)d_in[19];
    const float* crm1= (const float*)d_in[20];
    const float* crv1= (const float*)d_in[21];
    const float* cW2 = (const float*)d_in[22];
    const float* cb2 = (const float*)d_in[23];
    const float* cg2 = (const float*)d_in[24];
    const float* cbe2= (const float*)d_in[25];
    const float* crm2= (const float*)d_in[26];
    const float* crv2= (const float*)d_in[27];
    const float* cW3 = (const float*)d_in[28];
    const float* cb3 = (const float*)d_in[29];
    float* out = (float*)d_out;

    const int N = in_sizes[0] / DIN;     // 100000
    const int E = in_sizes[2];           // 1600000
    const int B = out_size / (HDIM + 2); // 256

    // graph prep
    zero_kernel<<<(N + 255) / 256, 256>>>(N, B);
    deg_kernel<<<(E + 255) / 256, 256>>>(ei, ew, E);
    dinv_kernel<<<(N + 255) / 256, 256>>>(N);
    scan_rowptr_kernel<<<1, 1024>>>(N);
    fill_kernel<<<(E + 255) / 256, 256>>>(ei, ew, E);

    // layer 1: aggregate in 128 dims first (linearity), then GEMM+BN+ReLU
    {
        float* ax = nullptr; cudaGetSymbolAddress((void**)&ax, g_ax);
        float* h1 = nullptr; cudaGetSymbolAddress((void**)&h1, g_h1);
        agg_kernel<DIN><<<(N + 7) / 8, 256>>>(x, ax, N);
        dim3 grid(2, (N + 127) / 128);
        gemm_bn_relu<DIN><<<grid, 256>>>(ax, W1, b1, g1, be1, rm1, rv1,
                                         nullptr, h1, N);
    }
    // layer 2: aggregate h1, GEMM+BN+ReLU + residual
    {
        float* h1 = nullptr; cudaGetSymbolAddress((void**)&h1, g_h1);
        float* ah = nullptr; cudaGetSymbolAddress((void**)&ah, g_ah);
        float* h2 = nullptr; cudaGetSymbolAddress((void**)&h2, g_h2);
        agg_kernel<HDIM><<<(N + 7) / 8, 256>>>(h1, ah, N);
        dim3 grid(2, (N + 127) / 128);
        gemm_bn_relu<HDIM><<<grid, 256>>>(ah, W2, b2, g2, be2, rm2, rv2,
                                          h1, h2, N);
    }

    // mean pool per graph (batch sorted -> contiguous ranges)
    gcount_kernel<<<(N + 255) / 256, 256>>>(bat, N);
    scan_goff_kernel<<<1, 256>>>(B);
    pool_kernel<<<B, HDIM>>>(out, B);

    // classifier head
    {
        float* emb = nullptr; cudaGetSymbolAddress((void**)&emb, g_emb);
        float* z1 = nullptr; cudaGetSymbolAddress((void**)&z1, g_z1);
        float* z2 = nullptr; cudaGetSymbolAddress((void**)&z2, g_z2);
        mlp_layer_kernel<<<B, 256>>>(emb, cW1, cb1, cg1, cbe1, crm1, crv1, z1, 256, 256);
        mlp_layer_kernel<<<B, 128>>>(z1, cW2, cb2, cg2, cbe2, crm2, crv2, z2, 256, 128);
        logits_kernel<<<(B * 2 + 63) / 64, 64>>>(cW3, cb3, out, B);
    }
}